// round 7
// baseline (speedup 1.0000x reference)
#include <cuda_runtime.h>
#include <math.h>
#include <float.h>
#include <stdint.h>

// Problem constants
#define M_ROWS 16384
#define INDIM  1024
#define H1D    1024
#define H2D    512
#define H3D    256
#define LATD   256
#define DDIM   32
#define KCODES 2048

// Output layout (floats): z | e | recon | loss, recon_loss, vq_loss
#define Z_OFF   0
#define E_OFF   (M_ROWS * LATD)
#define R_OFF   (E_OFF + M_ROWS * LATD)
#define SC_OFF  (R_OFF + M_ROWS * INDIM)

// Scratch (static device globals)
__device__ float g_h1[M_ROWS * H1D];
__device__ float g_h2[M_ROWS * H2D];
__device__ float g_h3[M_ROWS * H3D];
__device__ float g_vq_part[512];
__device__ float g_rec_part[1024];

// transposed decoder weights: Wt[n,k] = W[k,n]
#define WTD1 0
#define WTD2 (WTD1 + 256*256)
#define WTD3 (WTD2 + 512*256)
#define WTD4 (WTD3 + 1024*512)
__device__ float g_wt[WTD4 + 1024*1024];

// ============================================================================
// tf32 helpers (decoder only)
// ============================================================================
__device__ __forceinline__ float tf32_hi(float x) {
    return __uint_as_float(__float_as_uint(x) & 0xFFFFE000u);
}
__device__ __forceinline__ void split_hl(float x, float& hi, float& lo) {
    hi = tf32_hi(x);
    lo = tf32_hi(x - hi);
}
__device__ __forceinline__ void mma_m16n8k8(
    float* c, uint32_t a0, uint32_t a1, uint32_t a2, uint32_t a3,
    uint32_t b0, uint32_t b1)
{
    asm volatile(
        "mma.sync.aligned.m16n8k8.row.col.f32.tf32.tf32.f32 "
        "{%0,%1,%2,%3}, {%4,%5,%6,%7}, {%8,%9}, {%0,%1,%2,%3};"
        : "+f"(c[0]), "+f"(c[1]), "+f"(c[2]), "+f"(c[3])
        : "r"(a0), "r"(a1), "r"(a2), "r"(a3), "r"(b0), "r"(b1));
}

// ============================================================================
// DECODER: mma.sync 3xTF32 GEMM, 128x128 tile, BK=16, double-buffered
// hi/lo-split smem tiles (split once at staging), static buffer indexing.
// Dynamic smem: 2 bufs x 4 tiles x (128*20) floats = 80KB.
// ACT: 1=leaky, 2=sigmoid(+fused recon-loss partial)
// ============================================================================
#define SLD  20
#define DTILE (128 * SLD)          // floats per tile

template <int ACT>
__global__ __launch_bounds__(256) void gemm_tf32_mma(
    const float* __restrict__ A, const float* __restrict__ Bt,
    const float* __restrict__ bias, float* __restrict__ C,
    const float* __restrict__ xin, float* __restrict__ part,
    int M, int N, int K)
{
    extern __shared__ __align__(16) float ds[];

    const int t    = threadIdx.x;
    const int lane = t & 31;
    const int wid  = t >> 5;
    const int wm   = wid & 1;
    const int wn   = wid >> 1;
    const int g    = lane >> 2;
    const int tg   = lane & 3;
    const int bx   = blockIdx.x;
    const int by   = blockIdx.y;

    float acc[4][4][4];
#pragma unroll
    for (int i = 0; i < 4; i++)
#pragma unroll
        for (int j = 0; j < 4; j++)
#pragma unroll
            for (int k = 0; k < 4; k++) acc[i][j][k] = 0.f;

    const float* Ab = A  + (size_t)(by * 128) * K;
    const float* Bb = Bt + (size_t)(bx * 128) * K;

    const int r0l = t >> 2;
    const int c4l = (t & 3) * 4;

    float4 va[2], vb[2];

    auto LOADC = [&](int kt) {
#pragma unroll
        for (int i = 0; i < 2; i++) {
            const int r = r0l + i * 64;
            va[i] = *(const float4*)(Ab + (size_t)r * K + kt + c4l);
            vb[i] = *(const float4*)(Bb + (size_t)r * K + kt + c4l);
        }
    };
    auto STOREC = [&](float* sAhi, float* sAlo, float* sBhi, float* sBlo) {
#pragma unroll
        for (int i = 0; i < 2; i++) {
            const int r = r0l + i * 64;
            const int o = r * SLD + c4l;
            float4 h, l;
            split_hl(va[i].x, h.x, l.x); split_hl(va[i].y, h.y, l.y);
            split_hl(va[i].z, h.z, l.z); split_hl(va[i].w, h.w, l.w);
            *(float4*)&sAhi[o] = h;
            *(float4*)&sAlo[o] = l;
            split_hl(vb[i].x, h.x, l.x); split_hl(vb[i].y, h.y, l.y);
            split_hl(vb[i].z, h.z, l.z); split_hl(vb[i].w, h.w, l.w);
            *(float4*)&sBhi[o] = h;
            *(float4*)&sBlo[o] = l;
        }
    };

    const int abase0 = (wm * 64 + g) * SLD + tg;
    const int bbase0 = (wn * 32 + g) * SLD + tg;

    auto COMPUTE = [&](const float* sAhi, const float* sAlo,
                       const float* sBhi, const float* sBlo) {
#pragma unroll
        for (int kk = 0; kk < 16; kk += 8) {
            uint32_t ah[4][4], al[4][4];
            const int abase = abase0 + kk;
#pragma unroll
            for (int mf = 0; mf < 4; mf++) {
                const int o = abase + mf * 16 * SLD;
                ah[mf][0] = __float_as_uint(sAhi[o]);
                ah[mf][1] = __float_as_uint(sAhi[o + 8 * SLD]);
                ah[mf][2] = __float_as_uint(sAhi[o + 4]);
                ah[mf][3] = __float_as_uint(sAhi[o + 8 * SLD + 4]);
                al[mf][0] = __float_as_uint(sAlo[o]);
                al[mf][1] = __float_as_uint(sAlo[o + 8 * SLD]);
                al[mf][2] = __float_as_uint(sAlo[o + 4]);
                al[mf][3] = __float_as_uint(sAlo[o + 8 * SLD + 4]);
            }
            uint32_t bh[4][2], bl[4][2];
            const int bbase = bbase0 + kk;
#pragma unroll
            for (int nf = 0; nf < 4; nf++) {
                const int o = bbase + nf * 8 * SLD;
                bh[nf][0] = __float_as_uint(sBhi[o]);
                bh[nf][1] = __float_as_uint(sBhi[o + 4]);
                bl[nf][0] = __float_as_uint(sBlo[o]);
                bl[nf][1] = __float_as_uint(sBlo[o + 4]);
            }
#pragma unroll
            for (int mf = 0; mf < 4; mf++)
#pragma unroll
                for (int nf = 0; nf < 4; nf++)
                    mma_m16n8k8(acc[mf][nf], ah[mf][0], ah[mf][1], ah[mf][2], ah[mf][3],
                                bh[nf][0], bh[nf][1]);
#pragma unroll
            for (int mf = 0; mf < 4; mf++)
#pragma unroll
                for (int nf = 0; nf < 4; nf++)
                    mma_m16n8k8(acc[mf][nf], ah[mf][0], ah[mf][1], ah[mf][2], ah[mf][3],
                                bl[nf][0], bl[nf][1]);
#pragma unroll
            for (int mf = 0; mf < 4; mf++)
#pragma unroll
                for (int nf = 0; nf < 4; nf++)
                    mma_m16n8k8(acc[mf][nf], al[mf][0], al[mf][1], al[mf][2], al[mf][3],
                                bh[nf][0], bh[nf][1]);
        }
    };

    // buffer tile pointers (static)
    float* b0Ah = ds;                 float* b0Al = ds + DTILE;
    float* b0Bh = ds + 2 * DTILE;     float* b0Bl = ds + 3 * DTILE;
    float* b1Ah = ds + 4 * DTILE;     float* b1Al = ds + 5 * DTILE;
    float* b1Bh = ds + 6 * DTILE;     float* b1Bl = ds + 7 * DTILE;

    const int nch = K / 16;           // even for all layers

    LOADC(0);
    STOREC(b0Ah, b0Al, b0Bh, b0Bl);
    __syncthreads();

    for (int c = 0; c < nch; c += 2) {
        LOADC((c + 1) * 16);                     // c+1 < nch (nch even)
        COMPUTE(b0Ah, b0Al, b0Bh, b0Bl);
        STOREC(b1Ah, b1Al, b1Bh, b1Bl);
        __syncthreads();
        if (c + 2 < nch) {
            LOADC((c + 2) * 16);
            COMPUTE(b1Ah, b1Al, b1Bh, b1Bl);
            STOREC(b0Ah, b0Al, b0Bh, b0Bl);
            __syncthreads();
        } else {
            COMPUTE(b1Ah, b1Al, b1Bh, b1Bl);
        }
    }

    // epilogue
    const int rbase = by * 128 + wm * 64 + g;
    const int cbase = bx * 128 + wn * 32 + 2 * tg;
    float lsum = 0.f;
#pragma unroll
    for (int nf = 0; nf < 4; nf++) {
        const int c0 = cbase + nf * 8;
        const float b0 = bias[c0], b1 = bias[c0 + 1];
#pragma unroll
        for (int mf = 0; mf < 4; mf++) {
            const int r = rbase + mf * 16;
            float v0 = acc[mf][nf][0] + b0;
            float v1 = acc[mf][nf][1] + b1;
            float v2 = acc[mf][nf][2] + b0;
            float v3 = acc[mf][nf][3] + b1;
            if (ACT == 1) {
                v0 = (v0 > 0.f) ? v0 : 0.01f * v0;
                v1 = (v1 > 0.f) ? v1 : 0.01f * v1;
                v2 = (v2 > 0.f) ? v2 : 0.01f * v2;
                v3 = (v3 > 0.f) ? v3 : 0.01f * v3;
            } else if (ACT == 2) {
                v0 = 1.f / (1.f + expf(-v0));
                v1 = 1.f / (1.f + expf(-v1));
                v2 = 1.f / (1.f + expf(-v2));
                v3 = 1.f / (1.f + expf(-v3));
            }
            *(float2*)(C + (size_t)r * N + c0)       = make_float2(v0, v1);
            *(float2*)(C + (size_t)(r + 8) * N + c0) = make_float2(v2, v3);
            if (ACT == 2) {
                float2 x0 = *(const float2*)(xin + (size_t)r * N + c0);
                float2 x1 = *(const float2*)(xin + (size_t)(r + 8) * N + c0);
                float d0 = v0 - x0.x, d1 = v1 - x0.y;
                float d2 = v2 - x1.x, d3 = v3 - x1.y;
                lsum += d0 * d0 + d1 * d1 + d2 * d2 + d3 * d3;
            }
        }
    }

    if (ACT == 2) {
        // block reduction of lsum (last compute used buffer 1; ds[0..255] is buf0)
        float* sred = ds;
        __syncthreads();
        sred[t] = lsum;
        __syncthreads();
        for (int o = 128; o > 0; o >>= 1) {
            if (t < o) sred[t] += sred[t + o];
            __syncthreads();
        }
        if (t == 0) part[blockIdx.y * gridDim.x + blockIdx.x] = sred[0];
    }
}

// ============================================================================
// Weight transpose: Wt[N,K] = W[K,N]
// ============================================================================
__global__ void transpose_kernel(const float* __restrict__ in, float* __restrict__ out,
                                 int K, int N)
{
    __shared__ float tile[32][33];
    const int x  = blockIdx.x * 32 + threadIdx.x;
    const int y0 = blockIdx.y * 32;
    for (int j = threadIdx.y; j < 32; j += 8)
        tile[j][threadIdx.x] = in[(size_t)(y0 + j) * N + x];
    __syncthreads();
    const int xo  = y0 + threadIdx.x;
    const int yo0 = blockIdx.x * 32;
    for (int j = threadIdx.y; j < 32; j += 8)
        out[(size_t)(yo0 + j) * K + xo] = tile[threadIdx.x][j];
}

// ============================================================================
// ENCODER: fp32 SIMT GEMM. Per-acc-element arithmetic chain is IDENTICAL to
// the proven R2 kernel (fmaf over ascending k). BK=16 + statically-indexed
// double buffer: pure scheduling change, bitwise-identical output.
// ============================================================================
template <int ACT>
__global__ __launch_bounds__(256) void gemm_bias_act(
    const float* __restrict__ A, const float* __restrict__ W,
    const float* __restrict__ bias, float* __restrict__ C,
    int M, int N, int K)
{
    __shared__ __align__(16) float As[2][16][128];
    __shared__ __align__(16) float Bs[2][16][128];

    const int t  = threadIdx.x;
    const int tx = t & 15;
    const int ty = t >> 4;
    const int bx = blockIdx.x;
    const int by = blockIdx.y;

    const int a_row = t >> 1;
    const int a_vec = (t & 1) * 4;
    const float* Ap = A + (size_t)(by * 128 + a_row) * K + a_vec;

    const int b_row = t >> 5;               // 0..7
    const int b_col = (t & 31) * 4;
    const float* Wp = W + (size_t)b_row * N + bx * 128 + b_col;

    float acc[8][8];
#pragma unroll
    for (int i = 0; i < 8; i++)
#pragma unroll
        for (int j = 0; j < 8; j++) acc[i][j] = 0.f;

    float4 a0v, a1v, b0v, b1v;

    auto LOADC = [&](int kt) {
        a0v = *(const float4*)(Ap + kt);
        a1v = *(const float4*)(Ap + kt + 8);
        b0v = *(const float4*)(Wp + (size_t)kt * N);
        b1v = *(const float4*)(Wp + (size_t)(kt + 8) * N);
    };

    auto STOREC = [&](float (*Asb)[128], float (*Bsb)[128]) {
        Asb[a_vec + 0][a_row] = a0v.x;
        Asb[a_vec + 1][a_row] = a0v.y;
        Asb[a_vec + 2][a_row] = a0v.z;
        Asb[a_vec + 3][a_row] = a0v.w;
        Asb[a_vec + 8][a_row] = a1v.x;
        Asb[a_vec + 9][a_row] = a1v.y;
        Asb[a_vec + 10][a_row] = a1v.z;
        Asb[a_vec + 11][a_row] = a1v.w;
        *(float4*)&Bsb[b_row][b_col]     = b0v;
        *(float4*)&Bsb[b_row + 8][b_col] = b1v;
    };

    auto COMPUTE = [&](const float (*Asb)[128], const float (*Bsb)[128]) {
#pragma unroll
        for (int k = 0; k < 16; k++) {
            float4 x0 = *(const float4*)&Asb[k][ty * 8];
            float4 x1 = *(const float4*)&Asb[k][ty * 8 + 4];
            float4 y0 = *(const float4*)&Bsb[k][tx * 8];
            float4 y1 = *(const float4*)&Bsb[k][tx * 8 + 4];
            float av[8] = {x0.x, x0.y, x0.z, x0.w, x1.x, x1.y, x1.z, x1.w};
            float bv[8] = {y0.x, y0.y, y0.z, y0.w, y1.x, y1.y, y1.z, y1.w};
#pragma unroll
            for (int i = 0; i < 8; i++)
#pragma unroll
                for (int j = 0; j < 8; j++)
                    acc[i][j] = fmaf(av[i], bv[j], acc[i][j]);
        }
    };

    const int nch = K / 16;                 // even for all layers

    LOADC(0);
    STOREC(As[0], Bs[0]);
    __syncthreads();

    for (int c = 0; c < nch; c += 2) {
        LOADC((c + 1) * 16);
        COMPUTE(As[0], Bs[0]);
        STOREC(As[1], Bs[1]);
        __syncthreads();
        if (c + 2 < nch) {
            LOADC((c + 2) * 16);
            COMPUTE(As[1], Bs[1]);
            STOREC(As[0], Bs[0]);
            __syncthreads();
        } else {
            COMPUTE(As[1], Bs[1]);
        }
    }

    const int colBase = bx * 128 + tx * 8;
    float4 bb0 = *(const float4*)&bias[colBase];
    float4 bb1 = *(const float4*)&bias[colBase + 4];
    float bv[8] = {bb0.x, bb0.y, bb0.z, bb0.w, bb1.x, bb1.y, bb1.z, bb1.w};

#pragma unroll
    for (int i = 0; i < 8; i++) {
        const int row = by * 128 + ty * 8 + i;
        float v[8];
#pragma unroll
        for (int j = 0; j < 8; j++) {
            float x = acc[i][j] + bv[j];
            if (ACT == 1) x = (x > 0.f) ? x : 0.01f * x;
            v[j] = x;
        }
        float* Cp = C + (size_t)row * N + colBase;
        *(float4*)(Cp)     = make_float4(v[0], v[1], v[2], v[3]);
        *(float4*)(Cp + 4) = make_float4(v[4], v[5], v[6], v[7]);
    }
}

// ============================================================================
// Vector quantizer (reference-matching association; unchanged from R2)
// ============================================================================
#define VQ_CHUNK 256
__global__ __launch_bounds__(256) void vq_kernel(
    const float* __restrict__ z, const float* __restrict__ E,
    float* __restrict__ q_out, float* __restrict__ part)
{
    __shared__ __align__(16) float sE[VQ_CHUNK * DDIM];
    __shared__ float sEn[VQ_CHUNK];
    __shared__ float sred[256];

    const int t = threadIdx.x;
    const size_t row = (size_t)blockIdx.x * 256 + t;

    float4 zv[8];
    const float4* zp = (const float4*)(z + row * DDIM);
#pragma unroll
    for (int i = 0; i < 8; i++) zv[i] = zp[i];

    float zz = 0.f;
#pragma unroll
    for (int i = 0; i < 8; i++) {
        zz += zv[i].x * zv[i].x;
        zz += zv[i].y * zv[i].y;
        zz += zv[i].z * zv[i].z;
        zz += zv[i].w * zv[i].w;
    }

    float best = FLT_MAX;
    int bidx = 0;

    for (int c0 = 0; c0 < KCODES; c0 += VQ_CHUNK) {
        __syncthreads();
        const float4* Ep = (const float4*)(E + (size_t)c0 * DDIM);
        float4* sEp = (float4*)sE;
#pragma unroll
        for (int i = 0; i < 8; i++) sEp[t + i * 256] = Ep[t + i * 256];
        __syncthreads();
        {
            const float* e1 = sE + t * DDIM;
            float s = 0.f;
#pragma unroll
            for (int j = 0; j < DDIM; j++) s += e1[j] * e1[j];
            sEn[t] = s;
        }
        __syncthreads();

        for (int c = 0; c < VQ_CHUNK; c++) {
            const float4* e4 = (const float4*)(sE + c * DDIM);
            float dot = 0.f;
#pragma unroll
            for (int j = 0; j < 8; j++) {
                float4 ev = e4[j];
                dot = fmaf(zv[j].x, ev.x, dot);
                dot = fmaf(zv[j].y, ev.y, dot);
                dot = fmaf(zv[j].z, ev.z, dot);
                dot = fmaf(zv[j].w, ev.w, dot);
            }
            float d = (zz + sEn[c]) - 2.f * dot;
            if (d < best) { best = d; bidx = c0 + c; }
        }
    }

    const float4* eq = (const float4*)(E + (size_t)bidx * DDIM);
    float4* qo = (float4*)(q_out + row * DDIM);
    float s = 0.f;
#pragma unroll
    for (int j = 0; j < 8; j++) {
        float4 v = eq[j];
        qo[j] = v;
        float dx = v.x - zv[j].x, dy = v.y - zv[j].y;
        float dz = v.z - zv[j].z, dw = v.w - zv[j].w;
        s += dx * dx + dy * dy + dz * dz + dw * dw;
    }

    sred[t] = s;
    __syncthreads();
    for (int o = 128; o > 0; o >>= 1) {
        if (t < o) sred[t] += sred[t + o];
        __syncthreads();
    }
    if (t == 0) part[blockIdx.x] = sred[0];
}

// ============================================================================
// finalize: vq parts (512) + fused recon parts (1024) -> scalars
// ============================================================================
__global__ __launch_bounds__(512) void finalize_kernel(
    const float* __restrict__ vqp, const float* __restrict__ recp,
    float* __restrict__ out_sc)
{
    __shared__ float sv[512];
    __shared__ float sr[512];
    const int t = threadIdx.x;
    sv[t] = vqp[t];
    sr[t] = recp[t] + recp[t + 512];
    __syncthreads();
    for (int o = 256; o > 0; o >>= 1) {
        if (t < o) { sv[t] += sv[t + o]; sr[t] += sr[t + o]; }
        __syncthreads();
    }
    if (t == 0) {
        float vq_loss = 1.25f * sv[0] / (float)M_ROWS;
        float rec_loss = sr[0] / (float)M_ROWS;
        out_sc[0] = rec_loss + vq_loss;
        out_sc[1] = rec_loss;
        out_sc[2] = vq_loss;
    }
}

// ============================================================================
extern "C" void kernel_launch(void* const* d_in, const int* in_sizes, int n_in,
                              void* d_out, int out_size)
{
    const float* x   = (const float*)d_in[0];
    const float* We1 = (const float*)d_in[1];
    const float* be1 = (const float*)d_in[2];
    const float* We2 = (const float*)d_in[3];
    const float* be2 = (const float*)d_in[4];
    const float* We3 = (const float*)d_in[5];
    const float* be3 = (const float*)d_in[6];
    const float* We4 = (const float*)d_in[7];
    const float* be4 = (const float*)d_in[8];
    const float* E   = (const float*)d_in[9];
    const float* Wd1 = (const float*)d_in[10];
    const float* bd1 = (const float*)d_in[11];
    const float* Wd2 = (const float*)d_in[12];
    const float* bd2 = (const float*)d_in[13];
    const float* Wd3 = (const float*)d_in[14];
    const float* bd3 = (const float*)d_in[15];
    const float* Wd4 = (const float*)d_in[16];
    const float* bd4 = (const float*)d_in[17];

    float* out   = (float*)d_out;
    float* z     = out + Z_OFF;
    float* e     = out + E_OFF;
    float* recon = out + R_OFF;

    float *h1, *h2, *h3, *vqp, *recp, *wt;
    cudaGetSymbolAddress((void**)&h1,   g_h1);
    cudaGetSymbolAddress((void**)&h2,   g_h2);
    cudaGetSymbolAddress((void**)&h3,   g_h3);
    cudaGetSymbolAddress((void**)&vqp,  g_vq_part);
    cudaGetSymbolAddress((void**)&recp, g_rec_part);
    cudaGetSymbolAddress((void**)&wt,   g_wt);

    const dim3 blk(256);
    const dim3 tblk(32, 8);
    const int DSMEM = 2 * 4 * DTILE * 4;   // 81920 bytes

    cudaFuncSetAttribute(gemm_tf32_mma<1>, cudaFuncAttributeMaxDynamicSharedMemorySize, DSMEM);
    cudaFuncSetAttribute(gemm_tf32_mma<2>, cudaFuncAttributeMaxDynamicSharedMemorySize, DSMEM);

    // transpose decoder weights
    transpose_kernel<<<dim3(H3D/32,   LATD/32),  tblk>>>(Wd1, wt + WTD1, LATD, H3D);
    transpose_kernel<<<dim3(H2D/32,   H3D/32),   tblk>>>(Wd2, wt + WTD2, H3D, H2D);
    transpose_kernel<<<dim3(H1D/32,   H2D/32),   tblk>>>(Wd3, wt + WTD3, H2D, H1D);
    transpose_kernel<<<dim3(INDIM/32, H1D/32),   tblk>>>(Wd4, wt + WTD4, H1D, INDIM);

    // encoder (fp32 SIMT, exact R2 arithmetic chain)
    gemm_bias_act<1><<<dim3(H1D/128, 128), blk>>>(x,  We1, be1, h1, M_ROWS, H1D, INDIM);
    gemm_bias_act<1><<<dim3(H2D/128, 128), blk>>>(h1, We2, be2, h2, M_ROWS, H2D, H1D);
    gemm_bias_act<1><<<dim3(H3D/128, 128), blk>>>(h2, We3, be3, h3, M_ROWS, H3D, H2D);
    gemm_bias_act<0><<<dim3(LATD/128, 128), blk>>>(h3, We4, be4, z,  M_ROWS, LATD, H3D);

    // vector quantizer
    vq_kernel<<<512, 256>>>(z, E, e, vqp);

    // decoder (mma.sync 3xTF32, double-buffered; last layer fuses recon loss)
    gemm_tf32_mma<1><<<dim3(H3D/128, 128), blk, DSMEM>>>(e,  wt + WTD1, bd1, h3,    nullptr, nullptr, M_ROWS, H3D, LATD);
    gemm_tf32_mma<1><<<dim3(H2D/128, 128), blk, DSMEM>>>(h3, wt + WTD2, bd2, h2,    nullptr, nullptr, M_ROWS, H2D, H3D);
    gemm_tf32_mma<1><<<dim3(H1D/128, 128), blk, DSMEM>>>(h2, wt + WTD3, bd3, h1,    nullptr, nullptr, M_ROWS, H1D, H2D);
    gemm_tf32_mma<2><<<dim3(INDIM/128, 128), blk, DSMEM>>>(h1, wt + WTD4, bd4, recon, x, recp, M_ROWS, INDIM, H1D);

    // losses
    finalize_kernel<<<1, 512>>>(vqp, recp, out + SC_OFF);
}

// round 8
// speedup vs baseline: 1.0932x; 1.0932x over previous
#include <cuda_runtime.h>
#include <cuda_bf16.h>
#include <math.h>
#include <float.h>
#include <stdint.h>

// Problem constants
#define M_ROWS 16384
#define INDIM  1024
#define H1D    1024
#define H2D    512
#define H3D    256
#define LATD   256
#define DDIM   32
#define KCODES 2048

// Output layout (floats): z | e | recon | loss, recon_loss, vq_loss
#define Z_OFF   0
#define E_OFF   (M_ROWS * LATD)
#define R_OFF   (E_OFF + M_ROWS * LATD)
#define SC_OFF  (R_OFF + M_ROWS * INDIM)

// Scratch (static device globals)
__device__ float g_h1[M_ROWS * H1D];
__device__ float g_h2[M_ROWS * H2D];
__device__ float g_h3[M_ROWS * H3D];
__device__ float g_vq_part[512];
__device__ float g_rec_part[1024];

// transposed decoder weights: Wt[n,k] = W[k,n]
#define WTD1 0
#define WTD2 (WTD1 + 256*256)
#define WTD3 (WTD2 + 512*256)
#define WTD4 (WTD3 + 1024*512)
__device__ float g_wt[WTD4 + 1024*1024];

// ============================================================================
// bf16 split helpers: x ≈ hi + lo, hi = rn-bf16(x), lo = rn-bf16(x - hi)
// ============================================================================
__device__ __forceinline__ void split_pack2(float x0, float x1,
                                            uint32_t& hi, uint32_t& lo) {
    __nv_bfloat162 h = __floats2bfloat162_rn(x0, x1);
    float r0 = x0 - __bfloat162float(h.x);
    float r1 = x1 - __bfloat162float(h.y);
    __nv_bfloat162 l = __floats2bfloat162_rn(r0, r1);
    hi = *(uint32_t*)&h;
    lo = *(uint32_t*)&l;
}

__device__ __forceinline__ void mma_bf16(
    float* c, uint32_t a0, uint32_t a1, uint32_t a2, uint32_t a3,
    uint32_t b0, uint32_t b1)
{
    asm volatile(
        "mma.sync.aligned.m16n8k16.row.col.f32.bf16.bf16.f32 "
        "{%0,%1,%2,%3}, {%4,%5,%6,%7}, {%8,%9}, {%0,%1,%2,%3};"
        : "+f"(c[0]), "+f"(c[1]), "+f"(c[2]), "+f"(c[3])
        : "r"(a0), "r"(a1), "r"(a2), "r"(a3), "r"(b0), "r"(b1));
}

// ============================================================================
// DECODER: mma.sync 3xBF16 GEMM: C[M,N] = act(A[M,K] @ Bt[N,K]^T + bias)
// 128x128 CTA tile, 8 warps (2m x 4n), warp tile 64x32, BK=16.
// Tiles in smem as packed bf16 pairs (uint32 words): 8 data words/row,
// padded to stride 12 words (48B, 16B-aligned, conflict-free mod 32).
// Single-buffered, register prefetch of next chunk (R4-proven structure).
// ACT: 1=leaky, 2=sigmoid(+fused recon-loss partial)
// ============================================================================
#define SLW 12      // words per smem row (8 data + 4 pad)

template <int ACT>
__global__ __launch_bounds__(256) void gemm_bf16_mma(
    const float* __restrict__ A, const float* __restrict__ Bt,
    const float* __restrict__ bias, float* __restrict__ C,
    const float* __restrict__ xin, float* __restrict__ part,
    int M, int N, int K)
{
    __shared__ __align__(16) uint32_t sAh[128 * SLW];
    __shared__ __align__(16) uint32_t sAl[128 * SLW];
    __shared__ __align__(16) uint32_t sBh[128 * SLW];
    __shared__ __align__(16) uint32_t sBl[128 * SLW];
    __shared__ float sred[256];

    const int t    = threadIdx.x;
    const int lane = t & 31;
    const int wid  = t >> 5;
    const int wm   = wid & 1;       // 0..1 -> 64-row half (M)
    const int wn   = wid >> 1;      // 0..3 -> 32-col slice (N)
    const int g    = lane >> 2;     // 0..7
    const int tg   = lane & 3;      // 0..3
    const int bx   = blockIdx.x;
    const int by   = blockIdx.y;

    float acc[4][4][4];
#pragma unroll
    for (int i = 0; i < 4; i++)
#pragma unroll
        for (int j = 0; j < 4; j++)
#pragma unroll
            for (int k = 0; k < 4; k++) acc[i][j][k] = 0.f;

    const float* Ab = A  + (size_t)(by * 128) * K;
    const float* Bb = Bt + (size_t)(bx * 128) * K;

    // tile-load mapping: 128 rows x 16 fp32 = 512 float4; 256 thr -> 2 each
    // idx = t + i*256 ; row = idx/4 ; quad = idx%4 (fp32 cols quad*4..+3)
    const int lrow  = t >> 2;         // rows t/4 and t/4 + 64
    const int lquad = t & 3;

    float4 va[2], vb[2];

    // prefetch chunk 0
#pragma unroll
    for (int i = 0; i < 2; i++) {
        const int r = lrow + i * 64;
        va[i] = *(const float4*)(Ab + (size_t)r * K + lquad * 4);
        vb[i] = *(const float4*)(Bb + (size_t)r * K + lquad * 4);
    }

    const int nch = K / 16;
    for (int c = 0; c < nch; c++) {
        // stage current chunk (split fp32 -> hi/lo bf16 pairs)
#pragma unroll
        for (int i = 0; i < 2; i++) {
            const int r = lrow + i * 64;
            const int w = r * SLW + lquad * 2;   // word offset (uint2-aligned)
            uint32_t h0, l0, h1, l1;
            split_pack2(va[i].x, va[i].y, h0, l0);
            split_pack2(va[i].z, va[i].w, h1, l1);
            *(uint2*)&sAh[w] = make_uint2(h0, h1);
            *(uint2*)&sAl[w] = make_uint2(l0, l1);
            split_pack2(vb[i].x, vb[i].y, h0, l0);
            split_pack2(vb[i].z, vb[i].w, h1, l1);
            *(uint2*)&sBh[w] = make_uint2(h0, h1);
            *(uint2*)&sBl[w] = make_uint2(l0, l1);
        }
        __syncthreads();

        // prefetch next chunk
        if (c + 1 < nch) {
            const int kt = (c + 1) * 16;
#pragma unroll
            for (int i = 0; i < 2; i++) {
                const int r = lrow + i * 64;
                va[i] = *(const float4*)(Ab + (size_t)r * K + kt + lquad * 4);
                vb[i] = *(const float4*)(Bb + (size_t)r * K + kt + lquad * 4);
            }
        }

        // fragments: one m16n8k16 step covers the whole BK=16 chunk
        // A frag (16x16): a0 = row g,   word tg ; a1 = row g+8, word tg
        //                 a2 = row g,   word tg+4 ; a3 = row g+8, word tg+4
        // B frag (8x16):  b0 = row n=g, word tg ; b1 = row n=g, word tg+4
        {
            uint32_t ah[4][4], al[4][4];
            const int ab = (wm * 64 + g) * SLW + tg;
#pragma unroll
            for (int mf = 0; mf < 4; mf++) {
                const int o = ab + mf * 16 * SLW;
                ah[mf][0] = sAh[o];
                ah[mf][1] = sAh[o + 8 * SLW];
                ah[mf][2] = sAh[o + 4];
                ah[mf][3] = sAh[o + 8 * SLW + 4];
                al[mf][0] = sAl[o];
                al[mf][1] = sAl[o + 8 * SLW];
                al[mf][2] = sAl[o + 4];
                al[mf][3] = sAl[o + 8 * SLW + 4];
            }
            uint32_t bh[4][2], bl[4][2];
            const int bb = (wn * 32 + g) * SLW + tg;
#pragma unroll
            for (int nf = 0; nf < 4; nf++) {
                const int o = bb + nf * 8 * SLW;
                bh[nf][0] = sBh[o];
                bh[nf][1] = sBh[o + 4];
                bl[nf][0] = sBl[o];
                bl[nf][1] = sBl[o + 4];
            }
            // pass 1: hi*hi
#pragma unroll
            for (int mf = 0; mf < 4; mf++)
#pragma unroll
                for (int nf = 0; nf < 4; nf++)
                    mma_bf16(acc[mf][nf], ah[mf][0], ah[mf][1], ah[mf][2], ah[mf][3],
                             bh[nf][0], bh[nf][1]);
            // pass 2: hi*lo
#pragma unroll
            for (int mf = 0; mf < 4; mf++)
#pragma unroll
                for (int nf = 0; nf < 4; nf++)
                    mma_bf16(acc[mf][nf], ah[mf][0], ah[mf][1], ah[mf][2], ah[mf][3],
                             bl[nf][0], bl[nf][1]);
            // pass 3: lo*hi
#pragma unroll
            for (int mf = 0; mf < 4; mf++)
#pragma unroll
                for (int nf = 0; nf < 4; nf++)
                    mma_bf16(acc[mf][nf], al[mf][0], al[mf][1], al[mf][2], al[mf][3],
                             bh[nf][0], bh[nf][1]);
        }
        __syncthreads();
    }

    // epilogue: bias + act + float2 stores (+ fused recon loss for ACT==2)
    const int rbase = by * 128 + wm * 64 + g;
    const int cbase = bx * 128 + wn * 32 + 2 * tg;
    float lsum = 0.f;
#pragma unroll
    for (int nf = 0; nf < 4; nf++) {
        const int c0 = cbase + nf * 8;
        const float b0 = bias[c0], b1 = bias[c0 + 1];
#pragma unroll
        for (int mf = 0; mf < 4; mf++) {
            const int r = rbase + mf * 16;
            float v0 = acc[mf][nf][0] + b0;
            float v1 = acc[mf][nf][1] + b1;
            float v2 = acc[mf][nf][2] + b0;
            float v3 = acc[mf][nf][3] + b1;
            if (ACT == 1) {
                v0 = (v0 > 0.f) ? v0 : 0.01f * v0;
                v1 = (v1 > 0.f) ? v1 : 0.01f * v1;
                v2 = (v2 > 0.f) ? v2 : 0.01f * v2;
                v3 = (v3 > 0.f) ? v3 : 0.01f * v3;
            } else if (ACT == 2) {
                v0 = 1.f / (1.f + expf(-v0));
                v1 = 1.f / (1.f + expf(-v1));
                v2 = 1.f / (1.f + expf(-v2));
                v3 = 1.f / (1.f + expf(-v3));
            }
            *(float2*)(C + (size_t)r * N + c0)       = make_float2(v0, v1);
            *(float2*)(C + (size_t)(r + 8) * N + c0) = make_float2(v2, v3);
            if (ACT == 2) {
                float2 x0 = *(const float2*)(xin + (size_t)r * N + c0);
                float2 x1 = *(const float2*)(xin + (size_t)(r + 8) * N + c0);
                float d0 = v0 - x0.x, d1 = v1 - x0.y;
                float d2 = v2 - x1.x, d3 = v3 - x1.y;
                lsum += d0 * d0 + d1 * d1 + d2 * d2 + d3 * d3;
            }
        }
    }

    if (ACT == 2) {
        sred[t] = lsum;
        __syncthreads();
        for (int o = 128; o > 0; o >>= 1) {
            if (t < o) sred[t] += sred[t + o];
            __syncthreads();
        }
        if (t == 0) part[blockIdx.y * gridDim.x + blockIdx.x] = sred[0];
    }
}

// ============================================================================
// Weight transpose: Wt[N,K] = W[K,N]
// ============================================================================
__global__ void transpose_kernel(const float* __restrict__ in, float* __restrict__ out,
                                 int K, int N)
{
    __shared__ float tile[32][33];
    const int x  = blockIdx.x * 32 + threadIdx.x;
    const int y0 = blockIdx.y * 32;
    for (int j = threadIdx.y; j < 32; j += 8)
        tile[j][threadIdx.x] = in[(size_t)(y0 + j) * N + x];
    __syncthreads();
    const int xo  = y0 + threadIdx.x;
    const int yo0 = blockIdx.x * 32;
    for (int j = threadIdx.y; j < 32; j += 8)
        out[(size_t)(yo0 + j) * K + xo] = tile[threadIdx.x][j];
}

// ============================================================================
// ENCODER: fp32 SIMT GEMM — EXACT copy of the proven R2/R4 kernel
// (z numerics are load-bearing for the VQ argmin; already at fp32 roofline)
// ============================================================================
template <int ACT>
__global__ __launch_bounds__(256) void gemm_bias_act(
    const float* __restrict__ A, const float* __restrict__ W,
    const float* __restrict__ bias, float* __restrict__ C,
    int M, int N, int K)
{
    __shared__ __align__(16) float As[8][128];
    __shared__ __align__(16) float Bs[8][128];

    const int t  = threadIdx.x;
    const int tx = t & 15;
    const int ty = t >> 4;
    const int bx = blockIdx.x;
    const int by = blockIdx.y;

    const int a_row = t >> 1;
    const int a_vec = (t & 1) * 4;
    const float* Ap = A + (size_t)(by * 128 + a_row) * K + a_vec;

    const int b_row = t >> 5;
    const int b_col = (t & 31) * 4;
    const float* Wp = W + (size_t)b_row * N + bx * 128 + b_col;

    float acc[8][8];
#pragma unroll
    for (int i = 0; i < 8; i++)
#pragma unroll
        for (int j = 0; j < 8; j++) acc[i][j] = 0.f;

    float4 aF = *(const float4*)Ap;
    float4 bF = *(const float4*)Wp;

    for (int kt = 0; kt < K; kt += 8) {
        As[a_vec + 0][a_row] = aF.x;
        As[a_vec + 1][a_row] = aF.y;
        As[a_vec + 2][a_row] = aF.z;
        As[a_vec + 3][a_row] = aF.w;
        *(float4*)&Bs[b_row][b_col] = bF;
        __syncthreads();

        if (kt + 8 < K) {
            Ap += 8;
            Wp += (size_t)8 * N;
            aF = *(const float4*)Ap;
            bF = *(const float4*)Wp;
        }

#pragma unroll
        for (int k = 0; k < 8; k++) {
            float4 a0 = *(const float4*)&As[k][ty * 8];
            float4 a1 = *(const float4*)&As[k][ty * 8 + 4];
            float4 b0 = *(const float4*)&Bs[k][tx * 8];
            float4 b1 = *(const float4*)&Bs[k][tx * 8 + 4];
            float av[8] = {a0.x, a0.y, a0.z, a0.w, a1.x, a1.y, a1.z, a1.w};
            float bv[8] = {b0.x, b0.y, b0.z, b0.w, b1.x, b1.y, b1.z, b1.w};
#pragma unroll
            for (int i = 0; i < 8; i++)
#pragma unroll
                for (int j = 0; j < 8; j++)
                    acc[i][j] = fmaf(av[i], bv[j], acc[i][j]);
        }
        __syncthreads();
    }

    const int colBase = bx * 128 + tx * 8;
    float4 bb0 = *(const float4*)&bias[colBase];
    float4 bb1 = *(const float4*)&bias[colBase + 4];
    float bv[8] = {bb0.x, bb0.y, bb0.z, bb0.w, bb1.x, bb1.y, bb1.z, bb1.w};

#pragma unroll
    for (int i = 0; i < 8; i++) {
        const int row = by * 128 + ty * 8 + i;
        float v[8];
#pragma unroll
        for (int j = 0; j < 8; j++) {
            float x = acc[i][j] + bv[j];
            if (ACT == 1) x = (x > 0.f) ? x : 0.01f * x;
            v[j] = x;
        }
        float* Cp = C + (size_t)row * N + colBase;
        *(float4*)(Cp)     = make_float4(v[0], v[1], v[2], v[3]);
        *(float4*)(Cp + 4) = make_float4(v[4], v[5], v[6], v[7]);
    }
}

// ============================================================================
// Vector quantizer (reference-matching association; unchanged from R2)
// ============================================================================
#define VQ_CHUNK 256
__global__ __launch_bounds__(256) void vq_kernel(
    const float* __restrict__ z, const float* __restrict__ E,
    float* __restrict__ q_out, float* __restrict__ part)
{
    __shared__ __align__(16) float sE[VQ_CHUNK * DDIM];
    __shared__ float sEn[VQ_CHUNK];
    __shared__ float sred[256];

    const int t = threadIdx.x;
    const size_t row = (size_t)blockIdx.x * 256 + t;

    float4 zv[8];
    const float4* zp = (const float4*)(z + row * DDIM);
#pragma unroll
    for (int i = 0; i < 8; i++) zv[i] = zp[i];

    float zz = 0.f;
#pragma unroll
    for (int i = 0; i < 8; i++) {
        zz += zv[i].x * zv[i].x;
        zz += zv[i].y * zv[i].y;
        zz += zv[i].z * zv[i].z;
        zz += zv[i].w * zv[i].w;
    }

    float best = FLT_MAX;
    int bidx = 0;

    for (int c0 = 0; c0 < KCODES; c0 += VQ_CHUNK) {
        __syncthreads();
        const float4* Ep = (const float4*)(E + (size_t)c0 * DDIM);
        float4* sEp = (float4*)sE;
#pragma unroll
        for (int i = 0; i < 8; i++) sEp[t + i * 256] = Ep[t + i * 256];
        __syncthreads();
        {
            const float* e1 = sE + t * DDIM;
            float s = 0.f;
#pragma unroll
            for (int j = 0; j < DDIM; j++) s += e1[j] * e1[j];
            sEn[t] = s;
        }
        __syncthreads();

        for (int c = 0; c < VQ_CHUNK; c++) {
            const float4* e4 = (const float4*)(sE + c * DDIM);
            float dot = 0.f;
#pragma unroll
            for (int j = 0; j < 8; j++) {
                float4 ev = e4[j];
                dot = fmaf(zv[j].x, ev.x, dot);
                dot = fmaf(zv[j].y, ev.y, dot);
                dot = fmaf(zv[j].z, ev.z, dot);
                dot = fmaf(zv[j].w, ev.w, dot);
            }
            float d = (zz + sEn[c]) - 2.f * dot;
            if (d < best) { best = d; bidx = c0 + c; }
        }
    }

    const float4* eq = (const float4*)(E + (size_t)bidx * DDIM);
    float4* qo = (float4*)(q_out + row * DDIM);
    float s = 0.f;
#pragma unroll
    for (int j = 0; j < 8; j++) {
        float4 v = eq[j];
        qo[j] = v;
        float dx = v.x - zv[j].x, dy = v.y - zv[j].y;
        float dz = v.z - zv[j].z, dw = v.w - zv[j].w;
        s += dx * dx + dy * dy + dz * dz + dw * dw;
    }

    sred[t] = s;
    __syncthreads();
    for (int o = 128; o > 0; o >>= 1) {
        if (t < o) sred[t] += sred[t + o];
        __syncthreads();
    }
    if (t == 0) part[blockIdx.x] = sred[0];
}

// ============================================================================
// finalize: vq parts (512) + fused recon parts (1024) -> scalars
// ============================================================================
__global__ __launch_bounds__(512) void finalize_kernel(
    const float* __restrict__ vqp, const float* __restrict__ recp,
    float* __restrict__ out_sc)
{
    __shared__ float sv[512];
    __shared__ float sr[512];
    const int t = threadIdx.x;
    sv[t] = vqp[t];
    sr[t] = recp[t] + recp[t + 512];
    __syncthreads();
    for (int o = 256; o > 0; o >>= 1) {
        if (t < o) { sv[t] += sv[t + o]; sr[t] += sr[t + o]; }
        __syncthreads();
    }
    if (t == 0) {
        float vq_loss = 1.25f * sv[0] / (float)M_ROWS;
        float rec_loss = sr[0] / (float)M_ROWS;
        out_sc[0] = rec_loss + vq_loss;
        out_sc[1] = rec_loss;
        out_sc[2] = vq_loss;
    }
}

// ============================================================================
extern "C" void kernel_launch(void* const* d_in, const int* in_sizes, int n_in,
                              void* d_out, int out_size)
{
    const float* x   = (const float*)d_in[0];
    const float* We1 = (const float*)d_in[1];
    const float* be1 = (const float*)d_in[2];
    const float* We2 = (const float*)d_in[3];
    const float* be2 = (const float*)d_in[4];
    const float* We3 = (const float*)d_in[5];
    const float* be3 = (const float*)d_in[6];
    const float* We4 = (const float*)d_in[7];
    const float* be4 = (const float*)d_in[8];
    const float* E   = (const float*)d_in[9];
    const float* Wd1 = (const float*)d_in[10];
    const float* bd1 = (const float*)d_in[11];
    const float* Wd2 = (const float*)d_in[12];
    const float* bd2 = (const float*)d_in[13];
    const float* Wd3 = (const float*)d_in[14];
    const float* bd3 = (const float*)d_in[15];
    const float* Wd4 = (const float*)d_in[16];
    const float* bd4 = (const float*)d_in[17];

    float* out   = (float*)d_out;
    float* z     = out + Z_OFF;
    float* e     = out + E_OFF;
    float* recon = out + R_OFF;

    float *h1, *h2, *h3, *vqp, *recp, *wt;
    cudaGetSymbolAddress((void**)&h1,   g_h1);
    cudaGetSymbolAddress((void**)&h2,   g_h2);
    cudaGetSymbolAddress((void**)&h3,   g_h3);
    cudaGetSymbolAddress((void**)&vqp,  g_vq_part);
    cudaGetSymbolAddress((void**)&recp, g_rec_part);
    cudaGetSymbolAddress((void**)&wt,   g_wt);

    const dim3 blk(256);
    const dim3 tblk(32, 8);

    // transpose decoder weights
    transpose_kernel<<<dim3(H3D/32,   LATD/32),  tblk>>>(Wd1, wt + WTD1, LATD, H3D);
    transpose_kernel<<<dim3(H2D/32,   H3D/32),   tblk>>>(Wd2, wt + WTD2, H3D, H2D);
    transpose_kernel<<<dim3(H1D/32,   H2D/32),   tblk>>>(Wd3, wt + WTD3, H2D, H1D);
    transpose_kernel<<<dim3(INDIM/32, H1D/32),   tblk>>>(Wd4, wt + WTD4, H1D, INDIM);

    // encoder (fp32 SIMT, proven exact — at fp32 roofline)
    gemm_bias_act<1><<<dim3(H1D/128, 128), blk>>>(x,  We1, be1, h1, M_ROWS, H1D, INDIM);
    gemm_bias_act<1><<<dim3(H2D/128, 128), blk>>>(h1, We2, be2, h2, M_ROWS, H2D, H1D);
    gemm_bias_act<1><<<dim3(H3D/128, 128), blk>>>(h2, We3, be3, h3, M_ROWS, H3D, H2D);
    gemm_bias_act<0><<<dim3(LATD/128, 128), blk>>>(h3, We4, be4, z,  M_ROWS, LATD, H3D);

    // vector quantizer
    vq_kernel<<<512, 256>>>(z, E, e, vqp);

    // decoder (mma.sync 3xBF16; last layer fuses recon loss)
    gemm_bf16_mma<1><<<dim3(H3D/128, 128), blk>>>(e,  wt + WTD1, bd1, h3,    nullptr, nullptr, M_ROWS, H3D, LATD);
    gemm_bf16_mma<1><<<dim3(H2D/128, 128), blk>>>(h3, wt + WTD2, bd2, h2,    nullptr, nullptr, M_ROWS, H2D, H3D);
    gemm_bf16_mma<1><<<dim3(H1D/128, 128), blk>>>(h2, wt + WTD3, bd3, h1,    nullptr, nullptr, M_ROWS, H1D, H2D);
    gemm_bf16_mma<2><<<dim3(INDIM/128, 128), blk>>>(h1, wt + WTD4, bd4, recon, x, recp, M_ROWS, INDIM, H1D);

    // losses
    finalize_kernel<<<1, 512>>>(vqp, recp, out + SC_OFF);
}

// round 9
// speedup vs baseline: 1.1210x; 1.0255x over previous
#include <cuda_runtime.h>
#include <cuda_bf16.h>
#include <math.h>
#include <float.h>
#include <stdint.h>

// Problem constants
#define M_ROWS 16384
#define INDIM  1024
#define H1D    1024
#define H2D    512
#define H3D    256
#define LATD   256
#define DDIM   32
#define KCODES 2048

// Output layout (floats): z | e | recon | loss, recon_loss, vq_loss
#define Z_OFF   0
#define E_OFF   (M_ROWS * LATD)
#define R_OFF   (E_OFF + M_ROWS * LATD)
#define SC_OFF  (R_OFF + M_ROWS * INDIM)

// Scratch (static device globals)
__device__ float g_h1[M_ROWS * H1D];
__device__ float g_h2[M_ROWS * H2D];
__device__ float g_h3[M_ROWS * H3D];
__device__ float g_vq_part[512];
__device__ float g_rec_part[1024];

// transposed decoder weights: Wt[n,k] = W[k,n]
#define WTD1 0
#define WTD2 (WTD1 + 256*256)
#define WTD3 (WTD2 + 512*256)
#define WTD4 (WTD3 + 1024*512)
__device__ float g_wt[WTD4 + 1024*1024];

// ============================================================================
// Packed fp32x2 helpers (Blackwell): per-lane rn FMA == fmaf bitwise.
// ============================================================================
__device__ __forceinline__ unsigned long long pack2_bcast(float x) {
    unsigned long long r;
    asm("mov.b64 %0, {%1, %1};" : "=l"(r) : "f"(x));
    return r;
}
__device__ __forceinline__ void ffma2(unsigned long long& acc,
                                      unsigned long long a,
                                      unsigned long long b) {
    asm("fma.rn.f32x2 %0, %1, %2, %0;" : "+l"(acc) : "l"(a), "l"(b));
}
__device__ __forceinline__ void unpack2(unsigned long long v, float& lo, float& hi) {
    asm("mov.b64 {%0, %1}, %2;" : "=f"(lo), "=f"(hi) : "l"(v));
}

// ============================================================================
// bf16 split helpers (decoder)
// ============================================================================
__device__ __forceinline__ void split_pack2(float x0, float x1,
                                            uint32_t& hi, uint32_t& lo) {
    __nv_bfloat162 h = __floats2bfloat162_rn(x0, x1);
    float r0 = x0 - __bfloat162float(h.x);
    float r1 = x1 - __bfloat162float(h.y);
    __nv_bfloat162 l = __floats2bfloat162_rn(r0, r1);
    hi = *(uint32_t*)&h;
    lo = *(uint32_t*)&l;
}

__device__ __forceinline__ void mma_bf16(
    float* c, uint32_t a0, uint32_t a1, uint32_t a2, uint32_t a3,
    uint32_t b0, uint32_t b1)
{
    asm volatile(
        "mma.sync.aligned.m16n8k16.row.col.f32.bf16.bf16.f32 "
        "{%0,%1,%2,%3}, {%4,%5,%6,%7}, {%8,%9}, {%0,%1,%2,%3};"
        : "+f"(c[0]), "+f"(c[1]), "+f"(c[2]), "+f"(c[3])
        : "r"(a0), "r"(a1), "r"(a2), "r"(a3), "r"(b0), "r"(b1));
}

// ============================================================================
// DECODER: mma.sync 3xBF16 GEMM (unchanged from R8 — proven)
// ============================================================================
#define SLW 12

template <int ACT>
__global__ __launch_bounds__(256) void gemm_bf16_mma(
    const float* __restrict__ A, const float* __restrict__ Bt,
    const float* __restrict__ bias, float* __restrict__ C,
    const float* __restrict__ xin, float* __restrict__ part,
    int M, int N, int K)
{
    __shared__ __align__(16) uint32_t sAh[128 * SLW];
    __shared__ __align__(16) uint32_t sAl[128 * SLW];
    __shared__ __align__(16) uint32_t sBh[128 * SLW];
    __shared__ __align__(16) uint32_t sBl[128 * SLW];
    __shared__ float sred[256];

    const int t    = threadIdx.x;
    const int lane = t & 31;
    const int wid  = t >> 5;
    const int wm   = wid & 1;
    const int wn   = wid >> 1;
    const int g    = lane >> 2;
    const int tg   = lane & 3;
    const int bx   = blockIdx.x;
    const int by   = blockIdx.y;

    float acc[4][4][4];
#pragma unroll
    for (int i = 0; i < 4; i++)
#pragma unroll
        for (int j = 0; j < 4; j++)
#pragma unroll
            for (int k = 0; k < 4; k++) acc[i][j][k] = 0.f;

    const float* Ab = A  + (size_t)(by * 128) * K;
    const float* Bb = Bt + (size_t)(bx * 128) * K;

    const int lrow  = t >> 2;
    const int lquad = t & 3;

    float4 va[2], vb[2];
#pragma unroll
    for (int i = 0; i < 2; i++) {
        const int r = lrow + i * 64;
        va[i] = *(const float4*)(Ab + (size_t)r * K + lquad * 4);
        vb[i] = *(const float4*)(Bb + (size_t)r * K + lquad * 4);
    }

    const int nch = K / 16;
    for (int c = 0; c < nch; c++) {
#pragma unroll
        for (int i = 0; i < 2; i++) {
            const int r = lrow + i * 64;
            const int w = r * SLW + lquad * 2;
            uint32_t h0, l0, h1, l1;
            split_pack2(va[i].x, va[i].y, h0, l0);
            split_pack2(va[i].z, va[i].w, h1, l1);
            *(uint2*)&sAh[w] = make_uint2(h0, h1);
            *(uint2*)&sAl[w] = make_uint2(l0, l1);
            split_pack2(vb[i].x, vb[i].y, h0, l0);
            split_pack2(vb[i].z, vb[i].w, h1, l1);
            *(uint2*)&sBh[w] = make_uint2(h0, h1);
            *(uint2*)&sBl[w] = make_uint2(l0, l1);
        }
        __syncthreads();

        if (c + 1 < nch) {
            const int kt = (c + 1) * 16;
#pragma unroll
            for (int i = 0; i < 2; i++) {
                const int r = lrow + i * 64;
                va[i] = *(const float4*)(Ab + (size_t)r * K + kt + lquad * 4);
                vb[i] = *(const float4*)(Bb + (size_t)r * K + kt + lquad * 4);
            }
        }

        {
            uint32_t ah[4][4], al[4][4];
            const int ab = (wm * 64 + g) * SLW + tg;
#pragma unroll
            for (int mf = 0; mf < 4; mf++) {
                const int o = ab + mf * 16 * SLW;
                ah[mf][0] = sAh[o];
                ah[mf][1] = sAh[o + 8 * SLW];
                ah[mf][2] = sAh[o + 4];
                ah[mf][3] = sAh[o + 8 * SLW + 4];
                al[mf][0] = sAl[o];
                al[mf][1] = sAl[o + 8 * SLW];
                al[mf][2] = sAl[o + 4];
                al[mf][3] = sAl[o + 8 * SLW + 4];
            }
            uint32_t bh[4][2], bl[4][2];
            const int bb = (wn * 32 + g) * SLW + tg;
#pragma unroll
            for (int nf = 0; nf < 4; nf++) {
                const int o = bb + nf * 8 * SLW;
                bh[nf][0] = sBh[o];
                bh[nf][1] = sBh[o + 4];
                bl[nf][0] = sBl[o];
                bl[nf][1] = sBl[o + 4];
            }
#pragma unroll
            for (int mf = 0; mf < 4; mf++)
#pragma unroll
                for (int nf = 0; nf < 4; nf++)
                    mma_bf16(acc[mf][nf], ah[mf][0], ah[mf][1], ah[mf][2], ah[mf][3],
                             bh[nf][0], bh[nf][1]);
#pragma unroll
            for (int mf = 0; mf < 4; mf++)
#pragma unroll
                for (int nf = 0; nf < 4; nf++)
                    mma_bf16(acc[mf][nf], ah[mf][0], ah[mf][1], ah[mf][2], ah[mf][3],
                             bl[nf][0], bl[nf][1]);
#pragma unroll
            for (int mf = 0; mf < 4; mf++)
#pragma unroll
                for (int nf = 0; nf < 4; nf++)
                    mma_bf16(acc[mf][nf], al[mf][0], al[mf][1], al[mf][2], al[mf][3],
                             bh[nf][0], bh[nf][1]);
        }
        __syncthreads();
    }

    const int rbase = by * 128 + wm * 64 + g;
    const int cbase = bx * 128 + wn * 32 + 2 * tg;
    float lsum = 0.f;
#pragma unroll
    for (int nf = 0; nf < 4; nf++) {
        const int c0 = cbase + nf * 8;
        const float b0 = bias[c0], b1 = bias[c0 + 1];
#pragma unroll
        for (int mf = 0; mf < 4; mf++) {
            const int r = rbase + mf * 16;
            float v0 = acc[mf][nf][0] + b0;
            float v1 = acc[mf][nf][1] + b1;
            float v2 = acc[mf][nf][2] + b0;
            float v3 = acc[mf][nf][3] + b1;
            if (ACT == 1) {
                v0 = (v0 > 0.f) ? v0 : 0.01f * v0;
                v1 = (v1 > 0.f) ? v1 : 0.01f * v1;
                v2 = (v2 > 0.f) ? v2 : 0.01f * v2;
                v3 = (v3 > 0.f) ? v3 : 0.01f * v3;
            } else if (ACT == 2) {
                v0 = 1.f / (1.f + expf(-v0));
                v1 = 1.f / (1.f + expf(-v1));
                v2 = 1.f / (1.f + expf(-v2));
                v3 = 1.f / (1.f + expf(-v3));
            }
            *(float2*)(C + (size_t)r * N + c0)       = make_float2(v0, v1);
            *(float2*)(C + (size_t)(r + 8) * N + c0) = make_float2(v2, v3);
            if (ACT == 2) {
                float2 x0 = *(const float2*)(xin + (size_t)r * N + c0);
                float2 x1 = *(const float2*)(xin + (size_t)(r + 8) * N + c0);
                float d0 = v0 - x0.x, d1 = v1 - x0.y;
                float d2 = v2 - x1.x, d3 = v3 - x1.y;
                lsum += d0 * d0 + d1 * d1 + d2 * d2 + d3 * d3;
            }
        }
    }

    if (ACT == 2) {
        sred[t] = lsum;
        __syncthreads();
        for (int o = 128; o > 0; o >>= 1) {
            if (t < o) sred[t] += sred[t + o];
            __syncthreads();
        }
        if (t == 0) part[blockIdx.y * gridDim.x + blockIdx.x] = sred[0];
    }
}

// ============================================================================
// Weight transpose: Wt[N,K] = W[K,N]
// ============================================================================
__global__ void transpose_kernel(const float* __restrict__ in, float* __restrict__ out,
                                 int K, int N)
{
    __shared__ float tile[32][33];
    const int x  = blockIdx.x * 32 + threadIdx.x;
    const int y0 = blockIdx.y * 32;
    for (int j = threadIdx.y; j < 32; j += 8)
        tile[j][threadIdx.x] = in[(size_t)(y0 + j) * N + x];
    __syncthreads();
    const int xo  = y0 + threadIdx.x;
    const int yo0 = blockIdx.x * 32;
    for (int j = threadIdx.y; j < 32; j += 8)
        out[(size_t)(yo0 + j) * K + xo] = tile[threadIdx.x][j];
}

// ============================================================================
// ENCODER: fp32 SIMT GEMM via packed fma.rn.f32x2 (FFMA2).
// Pairing: acc2[i][j2] = (acc[i][2j2], acc[i][2j2+1]). Each lane of each pair
// accumulates fmaf(a_i[k], b_j[k], acc) over ascending k with rn rounding —
// BITWISE IDENTICAL to the proven R2 kernel. b pairs come straight from the
// float4 register pairs (no pack); a is broadcast-packed once per (k, i).
// ============================================================================
template <int ACT>
__global__ __launch_bounds__(256) void gemm_bias_act(
    const float* __restrict__ A, const float* __restrict__ W,
    const float* __restrict__ bias, float* __restrict__ C,
    int M, int N, int K)
{
    __shared__ __align__(16) float As[8][128];
    __shared__ __align__(16) float Bs[8][128];

    const int t  = threadIdx.x;
    const int tx = t & 15;
    const int ty = t >> 4;
    const int bx = blockIdx.x;
    const int by = blockIdx.y;

    const int a_row = t >> 1;
    const int a_vec = (t & 1) * 4;
    const float* Ap = A + (size_t)(by * 128 + a_row) * K + a_vec;

    const int b_row = t >> 5;
    const int b_col = (t & 31) * 4;
    const float* Wp = W + (size_t)b_row * N + bx * 128 + b_col;

    unsigned long long acc2[8][4];
#pragma unroll
    for (int i = 0; i < 8; i++)
#pragma unroll
        for (int j = 0; j < 4; j++) acc2[i][j] = 0ull;

    float4 aF = *(const float4*)Ap;
    float4 bF = *(const float4*)Wp;

    for (int kt = 0; kt < K; kt += 8) {
        As[a_vec + 0][a_row] = aF.x;
        As[a_vec + 1][a_row] = aF.y;
        As[a_vec + 2][a_row] = aF.z;
        As[a_vec + 3][a_row] = aF.w;
        *(float4*)&Bs[b_row][b_col] = bF;
        __syncthreads();

        if (kt + 8 < K) {
            Ap += 8;
            Wp += (size_t)8 * N;
            aF = *(const float4*)Ap;
            bF = *(const float4*)Wp;
        }

#pragma unroll
        for (int k = 0; k < 8; k++) {
            float4 a0 = *(const float4*)&As[k][ty * 8];
            float4 a1 = *(const float4*)&As[k][ty * 8 + 4];
            // b pairs: float4 register pairs reinterpreted as f32x2 operands
            ulonglong2 bA = *(const ulonglong2*)&Bs[k][tx * 8];
            ulonglong2 bB = *(const ulonglong2*)&Bs[k][tx * 8 + 4];
            unsigned long long bb[4] = {bA.x, bA.y, bB.x, bB.y};
            float av[8] = {a0.x, a0.y, a0.z, a0.w, a1.x, a1.y, a1.z, a1.w};
#pragma unroll
            for (int i = 0; i < 8; i++) {
                unsigned long long aa = pack2_bcast(av[i]);
#pragma unroll
                for (int j = 0; j < 4; j++)
                    ffma2(acc2[i][j], aa, bb[j]);
            }
        }
        __syncthreads();
    }

    const int colBase = bx * 128 + tx * 8;
    float4 bb0 = *(const float4*)&bias[colBase];
    float4 bb1 = *(const float4*)&bias[colBase + 4];
    float bv[8] = {bb0.x, bb0.y, bb0.z, bb0.w, bb1.x, bb1.y, bb1.z, bb1.w};

#pragma unroll
    for (int i = 0; i < 8; i++) {
        const int row = by * 128 + ty * 8 + i;
        float v[8];
#pragma unroll
        for (int j = 0; j < 4; j++)
            unpack2(acc2[i][j], v[2 * j], v[2 * j + 1]);
#pragma unroll
        for (int j = 0; j < 8; j++) {
            float x = v[j] + bv[j];
            if (ACT == 1) x = (x > 0.f) ? x : 0.01f * x;
            v[j] = x;
        }
        float* Cp = C + (size_t)row * N + colBase;
        *(float4*)(Cp)     = make_float4(v[0], v[1], v[2], v[3]);
        *(float4*)(Cp + 4) = make_float4(v[4], v[5], v[6], v[7]);
    }
}

// ============================================================================
// Vector quantizer (reference-matching association; unchanged from R2)
// ============================================================================
#define VQ_CHUNK 256
__global__ __launch_bounds__(256) void vq_kernel(
    const float* __restrict__ z, const float* __restrict__ E,
    float* __restrict__ q_out, float* __restrict__ part)
{
    __shared__ __align__(16) float sE[VQ_CHUNK * DDIM];
    __shared__ float sEn[VQ_CHUNK];
    __shared__ float sred[256];

    const int t = threadIdx.x;
    const size_t row = (size_t)blockIdx.x * 256 + t;

    float4 zv[8];
    const float4* zp = (const float4*)(z + row * DDIM);
#pragma unroll
    for (int i = 0; i < 8; i++) zv[i] = zp[i];

    float zz = 0.f;
#pragma unroll
    for (int i = 0; i < 8; i++) {
        zz += zv[i].x * zv[i].x;
        zz += zv[i].y * zv[i].y;
        zz += zv[i].z * zv[i].z;
        zz += zv[i].w * zv[i].w;
    }

    float best = FLT_MAX;
    int bidx = 0;

    for (int c0 = 0; c0 < KCODES; c0 += VQ_CHUNK) {
        __syncthreads();
        const float4* Ep = (const float4*)(E + (size_t)c0 * DDIM);
        float4* sEp = (float4*)sE;
#pragma unroll
        for (int i = 0; i < 8; i++) sEp[t + i * 256] = Ep[t + i * 256];
        __syncthreads();
        {
            const float* e1 = sE + t * DDIM;
            float s = 0.f;
#pragma unroll
            for (int j = 0; j < DDIM; j++) s += e1[j] * e1[j];
            sEn[t] = s;
        }
        __syncthreads();

        for (int c = 0; c < VQ_CHUNK; c++) {
            const float4* e4 = (const float4*)(sE + c * DDIM);
            float dot = 0.f;
#pragma unroll
            for (int j = 0; j < 8; j++) {
                float4 ev = e4[j];
                dot = fmaf(zv[j].x, ev.x, dot);
                dot = fmaf(zv[j].y, ev.y, dot);
                dot = fmaf(zv[j].z, ev.z, dot);
                dot = fmaf(zv[j].w, ev.w, dot);
            }
            float d = (zz + sEn[c]) - 2.f * dot;
            if (d < best) { best = d; bidx = c0 + c; }
        }
    }

    const float4* eq = (const float4*)(E + (size_t)bidx * DDIM);
    float4* qo = (float4*)(q_out + row * DDIM);
    float s = 0.f;
#pragma unroll
    for (int j = 0; j < 8; j++) {
        float4 v = eq[j];
        qo[j] = v;
        float dx = v.x - zv[j].x, dy = v.y - zv[j].y;
        float dz = v.z - zv[j].z, dw = v.w - zv[j].w;
        s += dx * dx + dy * dy + dz * dz + dw * dw;
    }

    sred[t] = s;
    __syncthreads();
    for (int o = 128; o > 0; o >>= 1) {
        if (t < o) sred[t] += sred[t + o];
        __syncthreads();
    }
    if (t == 0) part[blockIdx.x] = sred[0];
}

// ============================================================================
// finalize: vq parts (512) + fused recon parts (1024) -> scalars
// ============================================================================
__global__ __launch_bounds__(512) void finalize_kernel(
    const float* __restrict__ vqp, const float* __restrict__ recp,
    float* __restrict__ out_sc)
{
    __shared__ float sv[512];
    __shared__ float sr[512];
    const int t = threadIdx.x;
    sv[t] = vqp[t];
    sr[t] = recp[t] + recp[t + 512];
    __syncthreads();
    for (int o = 256; o > 0; o >>= 1) {
        if (t < o) { sv[t] += sv[t + o]; sr[t] += sr[t + o]; }
        __syncthreads();
    }
    if (t == 0) {
        float vq_loss = 1.25f * sv[0] / (float)M_ROWS;
        float rec_loss = sr[0] / (float)M_ROWS;
        out_sc[0] = rec_loss + vq_loss;
        out_sc[1] = rec_loss;
        out_sc[2] = vq_loss;
    }
}

// ============================================================================
extern "C" void kernel_launch(void* const* d_in, const int* in_sizes, int n_in,
                              void* d_out, int out_size)
{
    const float* x   = (const float*)d_in[0];
    const float* We1 = (const float*)d_in[1];
    const float* be1 = (const float*)d_in[2];
    const float* We2 = (const float*)d_in[3];
    const float* be2 = (const float*)d_in[4];
    const float* We3 = (const float*)d_in[5];
    const float* be3 = (const float*)d_in[6];
    const float* We4 = (const float*)d_in[7];
    const float* be4 = (const float*)d_in[8];
    const float* E   = (const float*)d_in[9];
    const float* Wd1 = (const float*)d_in[10];
    const float* bd1 = (const float*)d_in[11];
    const float* Wd2 = (const float*)d_in[12];
    const float* bd2 = (const float*)d_in[13];
    const float* Wd3 = (const float*)d_in[14];
    const float* bd3 = (const float*)d_in[15];
    const float* Wd4 = (const float*)d_in[16];
    const float* bd4 = (const float*)d_in[17];

    float* out   = (float*)d_out;
    float* z     = out + Z_OFF;
    float* e     = out + E_OFF;
    float* recon = out + R_OFF;

    float *h1, *h2, *h3, *vqp, *recp, *wt;
    cudaGetSymbolAddress((void**)&h1,   g_h1);
    cudaGetSymbolAddress((void**)&h2,   g_h2);
    cudaGetSymbolAddress((void**)&h3,   g_h3);
    cudaGetSymbolAddress((void**)&vqp,  g_vq_part);
    cudaGetSymbolAddress((void**)&recp, g_rec_part);
    cudaGetSymbolAddress((void**)&wt,   g_wt);

    const dim3 blk(256);
    const dim3 tblk(32, 8);

    // transpose decoder weights
    transpose_kernel<<<dim3(H3D/32,   LATD/32),  tblk>>>(Wd1, wt + WTD1, LATD, H3D);
    transpose_kernel<<<dim3(H2D/32,   H3D/32),   tblk>>>(Wd2, wt + WTD2, H3D, H2D);
    transpose_kernel<<<dim3(H1D/32,   H2D/32),   tblk>>>(Wd3, wt + WTD3, H2D, H1D);
    transpose_kernel<<<dim3(INDIM/32, H1D/32),   tblk>>>(Wd4, wt + WTD4, H1D, INDIM);

    // encoder (fp32 FFMA2 — bitwise identical to proven fmaf chains)
    gemm_bias_act<1><<<dim3(H1D/128, 128), blk>>>(x,  We1, be1, h1, M_ROWS, H1D, INDIM);
    gemm_bias_act<1><<<dim3(H2D/128, 128), blk>>>(h1, We2, be2, h2, M_ROWS, H2D, H1D);
    gemm_bias_act<1><<<dim3(H3D/128, 128), blk>>>(h2, We3, be3, h3, M_ROWS, H3D, H2D);
    gemm_bias_act<0><<<dim3(LATD/128, 128), blk>>>(h3, We4, be4, z,  M_ROWS, LATD, H3D);

    // vector quantizer
    vq_kernel<<<512, 256>>>(z, E, e, vqp);

    // decoder (mma.sync 3xBF16; last layer fuses recon loss)
    gemm_bf16_mma<1><<<dim3(H3D/128, 128), blk>>>(e,  wt + WTD1, bd1, h3,    nullptr, nullptr, M_ROWS, H3D, LATD);
    gemm_bf16_mma<1><<<dim3(H2D/128, 128), blk>>>(h3, wt + WTD2, bd2, h2,    nullptr, nullptr, M_ROWS, H2D, H3D);
    gemm_bf16_mma<1><<<dim3(H1D/128, 128), blk>>>(h2, wt + WTD3, bd3, h1,    nullptr, nullptr, M_ROWS, H1D, H2D);
    gemm_bf16_mma<2><<<dim3(INDIM/128, 128), blk>>>(h1, wt + WTD4, bd4, recon, x, recp, M_ROWS, INDIM, H1D);

    // losses
    finalize_kernel<<<1, 512>>>(vqp, recp, out + SC_OFF);
}